// round 15
// baseline (speedup 1.0000x reference)
#include <cuda_runtime.h>
#include <cstdint>
#include <cstddef>

#define L2E 1.4426950408889634f
typedef unsigned long long u64;

__device__ __align__(16) float g_ptab[30000u * 1536u]; // pre-projected vocab
__device__ __align__(16) float g_hidden[128 * 512];    // [B, 2H] final hidden

__device__ __forceinline__ float ex2c(float y) {
    y = fminf(fmaxf(y, -126.f), 126.f);
    float r; asm("ex2.approx.f32 %0, %1;" : "=f"(r) : "f"(y)); return r;
}
__device__ __forceinline__ float rcp_(float x) {
    float r; asm("rcp.approx.f32 %0, %1;" : "=f"(r) : "f"(x)); return r;
}
__device__ __forceinline__ float sig_(float x) { return rcp_(1.f + ex2c(-x * L2E)); }
__device__ __forceinline__ float tanh_(float x) {
    float u = ex2c(2.f * L2E * x);
    return (u - 1.f) * rcp_(u + 1.f);
}
__device__ __forceinline__ u64 fma2(u64 a, u64 b, u64 c) {
    u64 d; asm("fma.rn.f32x2 %0, %1, %2, %3;" : "=l"(d) : "l"(a), "l"(b), "l"(c)); return d;
}
__device__ __forceinline__ float hsum(u64 v) {
    float x, y; asm("mov.b64 {%0,%1}, %2;" : "=f"(x), "=f"(y) : "l"(v)); return x + y;
}
__device__ __forceinline__ void cluster_sync_() {
    asm volatile("barrier.cluster.arrive.aligned;" ::: "memory");
    asm volatile("barrier.cluster.wait.aligned;" ::: "memory");
}
__device__ __forceinline__ uint32_t mapa_(uint32_t saddr, int rank) {
    uint32_t ra;
    asm volatile("mapa.shared::cluster.u32 %0, %1, %2;" : "=r"(ra) : "r"(saddr), "r"(rank));
    return ra;
}
__device__ __forceinline__ void st_cluster_f32(uint32_t ra, float v) {
    asm volatile("st.shared::cluster.f32 [%0], %1;" :: "r"(ra), "f"(v));
}

// no-op kernel: pads the launch cycle so the ncu capture lands on k2_gru
__global__ void k0_dummy() {}

// ---------------------------------------------------------------------------
// K1: ptab[30000,1536] = emb @ [Wf;Wb]^T + b. (frozen — 512us)
// ---------------------------------------------------------------------------
#define AST 34
#define WST 34

__global__ void __launch_bounds__(256, 2)
k1_ptab(const float* __restrict__ emb,
        const float* __restrict__ Wf, const float* __restrict__ Wb,
        const float* __restrict__ bf, const float* __restrict__ bb)
{
    __shared__ __align__(16) float As[128 * AST];
    __shared__ __align__(16) float Ws[64 * WST];

    const int tid   = threadIdx.x;
    const int nBase = blockIdx.x * 64;
    const int mBase = blockIdx.y * 128;

    const float* Wsrc; const float* bsrc; int nOff;
    if (nBase < 768) { Wsrc = Wf; bsrc = bf; nOff = nBase; }
    else             { Wsrc = Wb; bsrc = bb; nOff = nBase - 768; }

    const int ty = tid >> 4;
    const int tx = tid & 15;

    u64 acc[8][4];
    #pragma unroll
    for (int j = 0; j < 8; ++j)
        #pragma unroll
        for (int n = 0; n < 4; ++n) acc[j][n] = 0ull;

    for (int kc = 0; kc < 256; kc += 32) {
        __syncthreads();
        #pragma unroll
        for (int q = 0; q < 4; ++q) {
            int idx = q * 256 + tid;
            int r = idx >> 3, c4 = (idx & 7) << 2;
            int row = mBase + r; if (row > 29999) row = 29999;
            float4 v = *reinterpret_cast<const float4*>(emb + (size_t)row * 256 + kc + c4);
            float* d = As + r * AST + c4;
            *reinterpret_cast<float2*>(d)     = make_float2(v.x, v.y);
            *reinterpret_cast<float2*>(d + 2) = make_float2(v.z, v.w);
        }
        #pragma unroll
        for (int q = 0; q < 2; ++q) {
            int idx = q * 256 + tid;
            int r = idx >> 3, c4 = (idx & 7) << 2;
            float4 v = *reinterpret_cast<const float4*>(Wsrc + (size_t)(nOff + r) * 256 + kc + c4);
            float* d = Ws + r * WST + c4;
            *reinterpret_cast<float2*>(d)     = make_float2(v.x, v.y);
            *reinterpret_cast<float2*>(d + 2) = make_float2(v.z, v.w);
        }
        __syncthreads();

        #pragma unroll
        for (int kk = 0; kk < 32; kk += 2) {
            u64 a2[8], w2[4];
            #pragma unroll
            for (int j = 0; j < 8; ++j)
                a2[j] = *reinterpret_cast<const u64*>(As + (ty * 8 + j) * AST + kk);
            #pragma unroll
            for (int n = 0; n < 4; ++n)
                w2[n] = *reinterpret_cast<const u64*>(Ws + (tx + 16 * n) * WST + kk);
            #pragma unroll
            for (int j = 0; j < 8; ++j)
                #pragma unroll
                for (int n = 0; n < 4; ++n)
                    acc[j][n] = fma2(a2[j], w2[n], acc[j][n]);
        }
    }

    float bias[4];
    #pragma unroll
    for (int n = 0; n < 4; ++n) bias[n] = bsrc[nOff + tx + 16 * n];

    #pragma unroll
    for (int j = 0; j < 8; ++j) {
        int row = mBase + ty * 8 + j;
        if (row < 30000) {
            float* o = g_ptab + (size_t)row * 1536 + nBase + tx;
            #pragma unroll
            for (int n = 0; n < 4; ++n)
                o[16 * n] = hsum(acc[j][n]) + bias[n];
        }
    }
}

// ---------------------------------------------------------------------------
// K2: recurrence. Grid 128, block 256, cluster 4.
// NEW mapping (L1-traffic cut): thread = 1 dim x 2 seqs.
//   warp w (0..7), lane l: dd=l>>2 (0..7), sp=l&3 (0..3)
//   dloc = 8w+dd (local dim 0..63); seqs n0=sp, n1=sp+4.
// Dot loop per 4-k: 3 w-loads (1 row/gate) + 2 h-loads = 5 LDS.128, 12 FFMA2
// (was 7 LDS.128 / 12 FFMA2). All loads bank-conflict-free at stride 260.
// ---------------------------------------------------------------------------
#define WSTR 260
#define HSTR 260
#define K2_SMEM ((192 * WSTR + 2 * 8 * HSTR) * 4)

__global__ void __cluster_dims__(4, 1, 1) __launch_bounds__(256, 1)
k2_gru(const int* __restrict__ tokens,
       const float* __restrict__ Whh_f, const float* __restrict__ bhh_f,
       const float* __restrict__ Whh_b, const float* __restrict__ bhh_b)
{
    extern __shared__ float smem[];
    float* Wsh  = smem;                    // 192 x WSTR
    float* hbuf = smem + 192 * WSTR;       // 2 x 8 x HSTR

    const int tid  = threadIdx.x;
    const int cid  = blockIdx.x >> 2;
    const int rank = blockIdx.x & 3;
    const int dir  = cid >> 4;
    const int qb   = cid & 15;

    const float* Whh = dir ? Whh_b : Whh_f;
    const float* bhh = dir ? bhh_b : bhh_f;

    const int w  = tid >> 5;               // warp 0..7
    const int l  = tid & 31;
    const int dd = l >> 2;                  // 0..7
    const int sp = l & 3;                   // 0..3
    const int dloc = 8 * w + dd;            // local dim 0..63
    const int n0 = sp, n1 = sp + 4;         // two seqs
    const int b0 = 8 * qb + n0, b1 = 8 * qb + n1;
    const int gd = 64 * rank + dloc;        // global dim

    for (int idx = tid; idx < 192 * 64; idx += 256) {
        int row = idx >> 6;
        int c4  = (idx & 63) << 2;
        int g = row >> 6, d = row & 63;
        float4 v = *reinterpret_cast<const float4*>(Whh + (size_t)(g * 256 + 64 * rank + d) * 256 + c4);
        *reinterpret_cast<float4*>(Wsh + row * WSTR + c4) = v;
    }
    for (int idx = tid; idx < 2 * 8 * HSTR; idx += 256) hbuf[idx] = 0.f;

    const float bR = bhh[0 * 256 + gd];
    const float bZ = bhh[1 * 256 + gd];
    const float bN = bhh[2 * 256 + gd];
    const size_t pbase = (size_t)dir * 768 + gd;

    // Hoisted DSMEM store addresses: [buf][seq][rank]
    uint32_t pa[2][2][4];
    #pragma unroll
    for (int buf = 0; buf < 2; ++buf) {
        uint32_t s0 = (uint32_t)__cvta_generic_to_shared(hbuf + buf * 8 * HSTR + n0 * HSTR + gd);
        uint32_t s1 = (uint32_t)__cvta_generic_to_shared(hbuf + buf * 8 * HSTR + n1 * HSTR + gd);
        #pragma unroll
        for (int rk = 0; rk < 4; ++rk) {
            pa[buf][0][rk] = mapa_(s0, rk);
            pa[buf][1][rk] = mapa_(s1, rk);
        }
    }

    // xg prefetch for t=0 (2 seqs x 3 gates, this dim)
    float xc[3][2];
    {
        int idx0 = (dir ? 511 : 0);
        int tok0 = tokens[b0 * 512 + idx0];
        int tok1 = tokens[b1 * 512 + idx0];
        const float* p0 = g_ptab + (size_t)tok0 * 1536 + pbase;
        const float* p1 = g_ptab + (size_t)tok1 * 1536 + pbase;
        #pragma unroll
        for (int g = 0; g < 3; ++g) { xc[g][0] = p0[g * 256]; xc[g][1] = p1[g * 256]; }
    }

    cluster_sync_();

    const float* wR = Wsh + (0 * 64 + dloc) * WSTR;
    const float* wZ = Wsh + (1 * 64 + dloc) * WSTR;
    const float* wN = Wsh + (2 * 64 + dloc) * WSTR;

    int cur = 0;
    for (int t = 0; t < 512; ++t) {
        // prefetch next step's xg (hidden under dot loop)
        float xn_[3][2];
        {
            int tn = (t < 511) ? t + 1 : 511;
            int idx = (dir ? 511 - tn : tn);
            int tok0 = tokens[b0 * 512 + idx];
            int tok1 = tokens[b1 * 512 + idx];
            const float* p0 = g_ptab + (size_t)tok0 * 1536 + pbase;
            const float* p1 = g_ptab + (size_t)tok1 * 1536 + pbase;
            #pragma unroll
            for (int g = 0; g < 3; ++g) { xn_[g][0] = p0[g * 256]; xn_[g][1] = p1[g * 256]; }
        }

        const float* hc0 = hbuf + cur * 8 * HSTR + n0 * HSTR;
        const float* hc1 = hbuf + cur * 8 * HSTR + n1 * HSTR;

        u64 aR0 = 0, aR1 = 0, aZ0 = 0, aZ1 = 0, aN0 = 0, aN1 = 0;
        #pragma unroll 8
        for (int kk = 0; kk < 256; kk += 4) {
            ulonglong2 h0 = *reinterpret_cast<const ulonglong2*>(hc0 + kk);
            ulonglong2 h1 = *reinterpret_cast<const ulonglong2*>(hc1 + kk);
            ulonglong2 r2 = *reinterpret_cast<const ulonglong2*>(wR + kk);
            ulonglong2 z2 = *reinterpret_cast<const ulonglong2*>(wZ + kk);
            ulonglong2 n2 = *reinterpret_cast<const ulonglong2*>(wN + kk);
            aR0 = fma2(r2.x, h0.x, aR0); aR0 = fma2(r2.y, h0.y, aR0);
            aR1 = fma2(r2.x, h1.x, aR1); aR1 = fma2(r2.y, h1.y, aR1);
            aZ0 = fma2(z2.x, h0.x, aZ0); aZ0 = fma2(z2.y, h0.y, aZ0);
            aZ1 = fma2(z2.x, h1.x, aZ1); aZ1 = fma2(z2.y, h1.y, aZ1);
            aN0 = fma2(n2.x, h0.x, aN0); aN0 = fma2(n2.y, h0.y, aN0);
            aN1 = fma2(n2.x, h1.x, aN1); aN1 = fma2(n2.y, h1.y, aN1);
        }

        float hrs0 = hsum(aR0) + bR, hrs1 = hsum(aR1) + bR;
        float hzs0 = hsum(aZ0) + bZ, hzs1 = hsum(aZ1) + bZ;
        float hns0 = hsum(aN0) + bN, hns1 = hsum(aN1) + bN;

        float hp0 = hc0[gd];
        float hp1 = hc1[gd];

        float r0 = sig_(xc[0][0] + hrs0);
        float z0 = sig_(xc[1][0] + hzs0);
        float nn0 = tanh_(xc[2][0] + r0 * hns0);
        float hnew0 = (1.f - z0) * nn0 + z0 * hp0;

        float r1 = sig_(xc[0][1] + hrs1);
        float z1 = sig_(xc[1][1] + hzs1);
        float nn1 = tanh_(xc[2][1] + r1 * hns1);
        float hnew1 = (1.f - z1) * nn1 + z1 * hp1;

        const int nxt = cur ^ 1;
        #pragma unroll
        for (int rk = 0; rk < 4; ++rk) {
            st_cluster_f32(pa[nxt][0][rk], hnew0);
            st_cluster_f32(pa[nxt][1][rk], hnew1);
        }

        cluster_sync_();
        #pragma unroll
        for (int g = 0; g < 3; ++g) { xc[g][0] = xn_[g][0]; xc[g][1] = xn_[g][1]; }
        cur = nxt;
    }

    // final h is in hbuf[cur]
    g_hidden[(size_t)b0 * 512 + dir * 256 + gd] = hbuf[cur * 8 * HSTR + n0 * HSTR + gd];
    g_hidden[(size_t)b1 * 512 + dir * 256 + gd] = hbuf[cur * 8 * HSTR + n1 * HSTR + gd];
}

// ---------------------------------------------------------------------------
// K3: logits[128,10] = hidden @ W_lin^T + b_lin.
// ---------------------------------------------------------------------------
__global__ void __launch_bounds__(320)
k3_head(const float* __restrict__ Wl, const float* __restrict__ bl,
        float* __restrict__ out)
{
    int b = blockIdx.x;
    int c = threadIdx.x >> 5;
    int lane = threadIdx.x & 31;

    const float* h = g_hidden + (size_t)b * 512;
    const float* wr = Wl + (size_t)c * 512;
    float acc = 0.f;
    #pragma unroll
    for (int k = lane; k < 512; k += 32) acc += h[k] * wr[k];
    #pragma unroll
    for (int s = 16; s > 0; s >>= 1) acc += __shfl_xor_sync(0xffffffffu, acc, s);
    if (lane == 0) out[b * 10 + c] = acc + bl[c];
}

// ---------------------------------------------------------------------------
extern "C" void kernel_launch(void* const* d_in, const int* in_sizes, int n_in,
                              void* d_out, int out_size)
{
    (void)in_sizes; (void)n_in; (void)out_size;
    const int*   tokens = (const int*)  d_in[0];
    const float* emb    = (const float*)d_in[1];
    const float* Wih_f  = (const float*)d_in[2];
    const float* Whh_f  = (const float*)d_in[3];
    const float* bih_f  = (const float*)d_in[4];
    const float* bhh_f  = (const float*)d_in[5];
    const float* Wih_b  = (const float*)d_in[6];
    const float* Whh_b  = (const float*)d_in[7];
    const float* bih_b  = (const float*)d_in[8];
    const float* bhh_b  = (const float*)d_in[9];
    const float* Wlin   = (const float*)d_in[10];
    const float* blin   = (const float*)d_in[11];
    float* out = (float*)d_out;

    cudaFuncSetAttribute(k2_gru, cudaFuncAttributeMaxDynamicSharedMemorySize, K2_SMEM);

    // launch cycle: d, d, k1, k2, d, k3  (k2 at position 4 of 6 — ncu target)
    k0_dummy<<<1, 32>>>();
    k0_dummy<<<1, 32>>>();

    dim3 g1(1536 / 64, (30000 + 127) / 128);
    k1_ptab<<<g1, 256>>>(emb, Wih_f, Wih_b, bih_f, bih_b);

    k2_gru<<<128, 256, K2_SMEM>>>(tokens, Whh_f, bhh_f, Whh_b, bhh_b);

    k0_dummy<<<1, 32>>>();

    k3_head<<<128, 320>>>(Wlin, blin, out);
}